// round 4
// baseline (speedup 1.0000x reference)
#include <cuda_runtime.h>

typedef unsigned long long u64;

#define LH 150
#define LQ 10
#define KI 10
#define NWARP 20
#define PSTR 12              // pair-row stride in u64 words (conflict-free)
#define PBUF (6 * PSTR)

// ---- packed f32x2 helpers -------------------------------------------------
__device__ __forceinline__ u64 fma2(u64 a, u64 b, u64 c) {
    u64 d;
    asm("fma.rn.f32x2 %0, %1, %2, %3;" : "=l"(d) : "l"(a), "l"(b), "l"(c));
    return d;
}
__device__ __forceinline__ u64 pack2(float lo, float hi) {
    u64 r;
    asm("mov.b64 %0, {%1, %2};" : "=l"(r) : "f"(lo), "f"(hi));
    return r;
}
__device__ __forceinline__ float2 unpack2(u64 p) {
    float2 v;
    asm("mov.b64 {%0, %1}, %2;" : "=f"(v.x), "=f"(v.y) : "l"(p));
    return v;
}

// One warp per batch element; lane l = (y0,x0) owns pixels (y0,x0),(y0+4,x0).
// v-grid in pair-row SMEM cells {v(R-1,xc-1), v(R+3,xc-1)}, stride 12 u64.
// Channel-paired packed weights live in ONE shared copy per block and are
// re-read per iteration via broadcast LDS.64 (opaque pointer defeats LICM),
// freeing ~90 registers -> 640-thread blocks, 5 warps/SMSP.
__global__ __launch_bounds__(NWARP * 32, 1)
void vin_kernel(const float* __restrict__ S,
                const float* __restrict__ Wh,
                const float* __restrict__ bh,
                const float* __restrict__ Wr,
                const float* __restrict__ Wq,
                const float* __restrict__ w,
                const float* __restrict__ Wfc,
                float* __restrict__ out, int B) {
    __shared__ u64 sbuf[NWARP][2][PBUF];
    __shared__ float sweff[10];
    __shared__ u64 wsh[45];    // packed transition weights {w[2c2][k], w[2c2+1][k]}
    __shared__ u64 wqsh[45];   // packed Wq, same layout

    const int tid = threadIdx.x;
    const int warp = tid >> 5;
    const int lane = tid & 31;

    // Block prologue: weff (warps 0..9) + packed weight staging (threads 320+)
    if (warp < 10) {
        float acc = 0.f;
        for (int c = lane; c < LH; c += 32) {
            float x = (warp < 9) ? __ldg(&Wh[c * 9 + warp]) : __ldg(&bh[c]);
            acc = fmaf(__ldg(&Wr[c]), x, acc);
        }
#pragma unroll
        for (int off = 16; off >= 1; off >>= 1)
            acc += __shfl_xor_sync(0xffffffffu, acc, off);
        if (lane == 0) sweff[warp] = acc;
    } else {
        int t2 = tid - 320;
        if (t2 < 45) {
            int c2 = t2 / 9, k = t2 % 9;
            wsh[t2] = pack2(__ldg(&w[(2 * c2) * 9 + k]),
                            __ldg(&w[(2 * c2 + 1) * 9 + k]));
        } else if (t2 < 90) {
            int t3 = t2 - 45;
            int c2 = t3 / 9, k = t3 % 9;
            wqsh[t3] = pack2(__ldg(&Wq[(2 * c2) * 9 + k]),
                             __ldg(&Wq[(2 * c2 + 1) * 9 + k]));
        }
    }
    __syncthreads();

    const int b = blockIdx.x * NWARP + warp;
    if (b >= B) return;                    // warp-uniform; no more block syncs
    const float* Sb = S + (long long)b * 66;

    u64* ub0 = sbuf[warp][0];
    u64* ub1 = sbuf[warp][1];

    const int y0 = lane >> 3, x0 = lane & 7;
    const int p  = y0 * PSTR + x0;
    const int ist = p + PSTR + 1;
    const int OFF[9] = {0, 1, 2, PSTR, PSTR + 1, PSTR + 2,
                        2 * PSTR, 2 * PSTR + 1, 2 * PSTR + 2};

    // Zero both buffers (borders stay zero -> implicit pad)
#pragma unroll
    for (int i = 0; i < 5; ++i) {
        int idx = lane + 32 * i;
        if (idx < PBUF) { ub0[idx] = 0ull; ub1[idx] = 0ull; }
    }
    __syncwarp();

    // Stage X as pair-rows
    float xa = Sb[lane], xb = Sb[lane + 32];
    ub0[ist] = pack2(xa, xb);
    if (y0 == 0) ub0[5 * PSTR + 1 + x0] = pack2(xb, 0.f);
    if (y0 == 3) ub0[1 + x0]            = pack2(0.f, xa);
    __syncwarp();

    // r = conv(X, W_eff, pad=1) + b_eff
    float r0 = sweff[9], r1 = r0;
#pragma unroll
    for (int k = 0; k < 9; ++k) {
        float2 n = unpack2(ub0[p + OFF[k]]);
        r0 = fmaf(sweff[k], n.x, r0);
        r1 = fmaf(sweff[k], n.y, r1);
    }
    __syncwarp();
    ub0[ist] = pack2(r0, r1);
    if (y0 == 0) ub0[5 * PSTR + 1 + x0] = pack2(r1, 0.f);
    if (y0 == 3) ub0[1 + x0]            = pack2(0.f, r0);
    __syncwarp();

    // qr[c] = conv(r, Wq[c], pad=1) -- loop-invariant, channel-packed
    u64 qr0p[5], qr1p[5];
#pragma unroll
    for (int c2 = 0; c2 < 5; ++c2) { qr0p[c2] = 0ull; qr1p[c2] = 0ull; }
#pragma unroll
    for (int k = 0; k < 9; ++k) {
        float2 nf = unpack2(ub0[p + OFF[k]]);
        u64 n0 = pack2(nf.x, nf.x);
        u64 n1 = pack2(nf.y, nf.y);
#pragma unroll
        for (int c2 = 0; c2 < 5; ++c2) {
            u64 wq = wqsh[c2 * 9 + k];
            qr0p[c2] = fma2(wq, n0, qr0p[c2]);
            qr1p[c2] = fma2(wq, n1, qr1p[c2]);
        }
    }

    // v0 = max_c qr
    float v0, v1;
    {
        float2 t0 = unpack2(qr0p[0]), t1 = unpack2(qr1p[0]);
        v0 = fmaxf(t0.x, t0.y); v1 = fmaxf(t1.x, t1.y);
#pragma unroll
        for (int c2 = 1; c2 < 5; ++c2) {
            t0 = unpack2(qr0p[c2]); t1 = unpack2(qr1p[c2]);
            v0 = fmaxf(v0, fmaxf(t0.x, t0.y));
            v1 = fmaxf(v1, fmaxf(t1.x, t1.y));
        }
    }
    __syncwarp();
    ub0[ist] = pack2(v0, v1);
    if (y0 == 0) ub0[5 * PSTR + 1 + x0] = pack2(v1, 0.f);
    if (y0 == 3) ub0[1 + x0]            = pack2(0.f, v0);

    // K-1 = 9 sweeps: v <- max_c( qr[c] + conv(v, w[c]) )
    const u64* src = ub0;
    u64* dst = ub1;
#pragma unroll 1
    for (int it = 0; it < KI - 1; ++it) {
        // Opaque copy of the weight pointer: ptxas cannot prove the 45
        // broadcast LDS.64 below are loop-invariant, so they are NOT hoisted
        // into 90 registers.
        const u64* wv = wsh;
        asm volatile("" : "+l"(wv));
        __syncwarp();
        u64 a0[5], a1[5];
#pragma unroll
        for (int k = 0; k < 9; ++k) {
            float2 nf = unpack2(src[p + OFF[k]]);
            u64 n0 = pack2(nf.x, nf.x);
            u64 n1 = pack2(nf.y, nf.y);
            if (k == 0) {
#pragma unroll
                for (int c2 = 0; c2 < 5; ++c2) {
                    u64 wk = wv[c2 * 9];
                    a0[c2] = fma2(wk, n0, qr0p[c2]);
                    a1[c2] = fma2(wk, n1, qr1p[c2]);
                }
            } else {
#pragma unroll
                for (int c2 = 0; c2 < 5; ++c2) {
                    u64 wk = wv[c2 * 9 + k];
                    a0[c2] = fma2(wk, n0, a0[c2]);
                    a1[c2] = fma2(wk, n1, a1[c2]);
                }
            }
        }
        float2 t0 = unpack2(a0[0]), t1 = unpack2(a1[0]);
        float m0 = fmaxf(t0.x, t0.y), m1 = fmaxf(t1.x, t1.y);
#pragma unroll
        for (int c2 = 1; c2 < 5; ++c2) {
            t0 = unpack2(a0[c2]); t1 = unpack2(a1[c2]);
            m0 = fmaxf(m0, fmaxf(t0.x, t0.y));
            m1 = fmaxf(m1, fmaxf(t1.x, t1.y));
        }
        dst[ist] = pack2(m0, m1);
        if (y0 == 0) dst[5 * PSTR + 1 + x0] = pack2(m1, 0.f);
        if (y0 == 3) dst[1 + x0]            = pack2(0.f, m0);
        u64* tmp = (u64*)src; src = dst; dst = tmp;
    }
    __syncwarp();

    // Final conv at the selected pixel + FC head (single owning lane)
    const int s1 = (int)Sb[64];
    const int s2 = (int)Sb[65];
    const int psel = s1 * 8 + s2;
    if (lane == (psel & 31)) {
        const bool hi = psel >= 32;
        u64 accp[5];
#pragma unroll
        for (int c2 = 0; c2 < 5; ++c2) accp[c2] = hi ? qr1p[c2] : qr0p[c2];
#pragma unroll
        for (int k = 0; k < 9; ++k) {
            const int dy = k / 3, dx = k % 3;
            const int rr = s1 - 1 + dy;
            const int xc = s2 + dx;
            float nn;
            if (rr <= 3) nn = unpack2(src[(rr + 1) * PSTR + xc]).x;
            else         nn = unpack2(src[(rr - 3) * PSTR + xc]).y;
            u64 np = pack2(nn, nn);
#pragma unroll
            for (int c2 = 0; c2 < 5; ++c2)
                accp[c2] = fma2(wsh[c2 * 9 + k], np, accp[c2]);
        }
        float lg[8];
#pragma unroll
        for (int j = 0; j < 8; ++j) lg[j] = 0.f;
#pragma unroll
        for (int c2 = 0; c2 < 5; ++c2) {
            float2 q = unpack2(accp[c2]);
#pragma unroll
            for (int j = 0; j < 8; ++j) {
                lg[j] = fmaf(q.x, __ldg(&Wfc[j * 10 + 2 * c2]), lg[j]);
                lg[j] = fmaf(q.y, __ldg(&Wfc[j * 10 + 2 * c2 + 1]), lg[j]);
            }
        }
#pragma unroll
        for (int j = 0; j < 8; ++j) out[(long long)b * 8 + j] = lg[j];
    }
}

extern "C" void kernel_launch(void* const* d_in, const int* in_sizes, int n_in,
                              void* d_out, int out_size) {
    const float* S   = (const float*)d_in[0];
    const float* Wh  = (const float*)d_in[1];
    const float* bh  = (const float*)d_in[2];
    const float* Wr  = (const float*)d_in[3];
    const float* Wq  = (const float*)d_in[4];
    const float* w   = (const float*)d_in[5];
    const float* Wfc = (const float*)d_in[6];
    float* out = (float*)d_out;

    const int B = in_sizes[0] / 66;
    const int grid = (B + NWARP - 1) / NWARP;
    vin_kernel<<<grid, NWARP * 32>>>(S, Wh, bh, Wr, Wq, w, Wfc, out, B);
}

// round 6
// speedup vs baseline: 1.4124x; 1.4124x over previous
#include <cuda_runtime.h>

typedef unsigned long long u64;

#define LH 150
#define LQ 10
#define KI 10
#define NWARP 10

// ---- packed f32x2 helpers -------------------------------------------------
__device__ __forceinline__ u64 fma2(u64 a, u64 b, u64 c) {
    u64 d;
    asm("fma.rn.f32x2 %0, %1, %2, %3;" : "=l"(d) : "l"(a), "l"(b), "l"(c));
    return d;
}
__device__ __forceinline__ u64 pack2(float lo, float hi) {
    u64 r;
    asm("mov.b64 %0, {%1, %2};" : "=l"(r) : "f"(lo), "f"(hi));
    return r;
}
__device__ __forceinline__ u64 splat2(float x) {
    u64 r;
    asm("mov.b64 %0, {%1, %1};" : "=l"(r) : "f"(x));
    return r;
}
__device__ __forceinline__ float2 unpack2(u64 p) {
    float2 v;
    asm("mov.b64 {%0, %1}, %2;" : "=f"(v.x), "=f"(v.y) : "l"(p));
    return v;
}

// Register-resident 3x3 stencil halo exchange via warp shuffles.
// Lane l = (y0 = l>>3, x0 = l&7) holds vA = v(y0,x0), vB = v(y0+4,x0).
// Row exchange: shfl +-8 (mod 32); the A/B pair straddles the row-3/4 seam,
// so one shfl pair provides both pixels' rows (seam fixed by SEL).
// Column exchange: shfl +-1; edge zeros applied AFTER the shuffle.
// ALL shuffles are unconditional (full-mask shfl.sync under divergence is UB
// -- that was the R5 bug); boundary handling is pure register selects.
__device__ __forceinline__ void stencil9(float vA, float vB, int lane,
                                         int y0, int x0,
                                         float* nA, float* nB) {
    const unsigned m = 0xffffffffu;
    const int ln = (lane + 24) & 31;    // north source lane (y0-1 mod 4)
    const int ls = (lane + 8) & 31;     // south source lane (y0+1 mod 4)
    const float sA = __shfl_sync(m, vA, ln);
    const float sB = __shfl_sync(m, vB, ln);
    const float tA = __shfl_sync(m, vA, ls);
    const float tB = __shfl_sync(m, vB, ls);
    const float nNA = y0 ? sA : 0.f;          // y0==0: row -1 = 0
    const float nNB = y0 ? sB : sA;           // y0==0: row 3 = src.vA
    const float nSA = (y0 < 3) ? tA : tB;     // y0==3: row 4 = src.vB
    const float nSB = (y0 < 3) ? tB : 0.f;    // y0==3: row 8 = 0

    const int lw = (lane + 31) & 31, le = (lane + 1) & 31;
    const float uNA = __shfl_sync(m, nNA, lw);
    const float uNB = __shfl_sync(m, nNB, lw);
    const float uCA = __shfl_sync(m, vA,  lw);
    const float uCB = __shfl_sync(m, vB,  lw);
    const float uSA = __shfl_sync(m, nSA, lw);
    const float uSB = __shfl_sync(m, nSB, lw);
    const float eNA = __shfl_sync(m, nNA, le);
    const float eNB = __shfl_sync(m, nNB, le);
    const float eCA = __shfl_sync(m, vA,  le);
    const float eCB = __shfl_sync(m, vB,  le);
    const float eSA = __shfl_sync(m, nSA, le);
    const float eSB = __shfl_sync(m, nSB, le);
    const bool hw = (x0 != 0), he = (x0 != 7);

    nA[0] = hw ? uNA : 0.f; nA[1] = nNA; nA[2] = he ? eNA : 0.f;
    nA[3] = hw ? uCA : 0.f; nA[4] = vA;  nA[5] = he ? eCA : 0.f;
    nA[6] = hw ? uSA : 0.f; nA[7] = nSA; nA[8] = he ? eSA : 0.f;
    nB[0] = hw ? uNB : 0.f; nB[1] = nNB; nB[2] = he ? eNB : 0.f;
    nB[3] = hw ? uCB : 0.f; nB[4] = vB;  nB[5] = he ? eCB : 0.f;
    nB[6] = hw ? uSB : 0.f; nB[7] = nSB; nB[8] = he ? eSB : 0.f;
}

// One warp per batch element; everything register-resident; NO smem access
// and no barriers in the iteration loop.
__global__ __launch_bounds__(NWARP * 32, 1)
void vin_kernel(const float* __restrict__ S,
                const float* __restrict__ Wh,
                const float* __restrict__ bh,
                const float* __restrict__ Wr,
                const float* __restrict__ Wq,
                const float* __restrict__ w,
                const float* __restrict__ Wfc,
                float* __restrict__ out, int B) {
    __shared__ float sweff[10];
    __shared__ u64 wsh[45];    // packed transition weights {w[2c2][k], w[2c2+1][k]}
    __shared__ u64 wqsh[45];   // packed Wq, same layout

    const int tid = threadIdx.x;
    const int warp = tid >> 5;
    const int lane = tid & 31;

    // One-time staging: packed weights (threads 0..89)
    if (tid < 45) {
        const int c2 = tid / 9, k = tid % 9;
        wsh[tid] = pack2(__ldg(&w[(2 * c2) * 9 + k]),
                         __ldg(&w[(2 * c2 + 1) * 9 + k]));
    } else if (tid < 90) {
        const int t = tid - 45;
        const int c2 = t / 9, k = t % 9;
        wqsh[t] = pack2(__ldg(&Wq[(2 * c2) * 9 + k]),
                        __ldg(&Wq[(2 * c2 + 1) * 9 + k]));
    }
    // weff: collapse 150-ch hidden conv + 1x1 readout (warp j -> output j)
    {
        float acc = 0.f;
        for (int c = lane; c < LH; c += 32) {
            float x = (warp < 9) ? __ldg(&Wh[c * 9 + warp]) : __ldg(&bh[c]);
            acc = fmaf(__ldg(&Wr[c]), x, acc);
        }
#pragma unroll
        for (int off = 16; off >= 1; off >>= 1)
            acc += __shfl_xor_sync(0xffffffffu, acc, off);
        if (lane == 0) sweff[warp] = acc;
    }
    __syncthreads();

    const int b = blockIdx.x * NWARP + warp;
    if (b >= B) return;                    // warp-uniform; no syncs below
    const float* Sb = S + (long long)b * 66;

    const int y0 = lane >> 3, x0 = lane & 7;

    // Per-warp register copy of packed transition weights (broadcast LDS, once)
    u64 wp[45];
#pragma unroll
    for (int i = 0; i < 45; ++i) wp[i] = wsh[i];

    // X in registers
    float vA = Sb[lane];
    float vB = Sb[lane + 32];

    float nA[9], nB[9];

    // r = conv(X, W_eff, pad=1) + b_eff
    stencil9(vA, vB, lane, y0, x0, nA, nB);
    float r0 = sweff[9], r1 = r0;
#pragma unroll
    for (int k = 0; k < 9; ++k) {
        r0 = fmaf(sweff[k], nA[k], r0);
        r1 = fmaf(sweff[k], nB[k], r1);
    }

    // qr[c] = conv(r, Wq[c], pad=1)  (loop-invariant, channel-packed)
    u64 qr0p[5], qr1p[5];
    stencil9(r0, r1, lane, y0, x0, nA, nB);
#pragma unroll
    for (int k = 0; k < 9; ++k) {
        const u64 s0 = splat2(nA[k]);
        const u64 s1 = splat2(nB[k]);
#pragma unroll
        for (int c2 = 0; c2 < 5; ++c2) {
            const u64 wq = wqsh[c2 * 9 + k];          // broadcast LDS, one-time
            qr0p[c2] = (k == 0) ? fma2(wq, s0, 0ull) : fma2(wq, s0, qr0p[c2]);
            qr1p[c2] = (k == 0) ? fma2(wq, s1, 0ull) : fma2(wq, s1, qr1p[c2]);
        }
    }

    // v = max_c qr
    {
        float2 t0 = unpack2(qr0p[0]), t1 = unpack2(qr1p[0]);
        vA = fmaxf(t0.x, t0.y); vB = fmaxf(t1.x, t1.y);
#pragma unroll
        for (int c2 = 1; c2 < 5; ++c2) {
            t0 = unpack2(qr0p[c2]); t1 = unpack2(qr1p[c2]);
            vA = fmaxf(vA, fmaxf(t0.x, t0.y));
            vB = fmaxf(vB, fmaxf(t1.x, t1.y));
        }
    }

    // K-1 = 9 sweeps: v <- max_c( qr[c] + conv(v, w[c]) ), all in registers
#pragma unroll 1
    for (int it = 0; it < KI - 1; ++it) {
        stencil9(vA, vB, lane, y0, x0, nA, nB);
        u64 a0[5], a1[5];
#pragma unroll
        for (int k = 0; k < 9; ++k) {
            const u64 s0 = splat2(nA[k]);
            const u64 s1 = splat2(nB[k]);
#pragma unroll
            for (int c2 = 0; c2 < 5; ++c2) {
                const u64 wk = wp[c2 * 9 + k];
                a0[c2] = (k == 0) ? fma2(wk, s0, qr0p[c2]) : fma2(wk, s0, a0[c2]);
                a1[c2] = (k == 0) ? fma2(wk, s1, qr1p[c2]) : fma2(wk, s1, a1[c2]);
            }
        }
        float2 t0 = unpack2(a0[0]), t1 = unpack2(a1[0]);
        float m0 = fmaxf(t0.x, t0.y), m1 = fmaxf(t1.x, t1.y);
#pragma unroll
        for (int c2 = 1; c2 < 5; ++c2) {
            t0 = unpack2(a0[c2]); t1 = unpack2(a1[c2]);
            m0 = fmaxf(m0, fmaxf(t0.x, t0.y));
            m1 = fmaxf(m1, fmaxf(t1.x, t1.y));
        }
        vA = m0; vB = m1;
    }

    // Final q = qr + conv(v, w)  (same body, no max), then pixel-select + FC
    u64 a0[5], a1[5];
    stencil9(vA, vB, lane, y0, x0, nA, nB);
#pragma unroll
    for (int k = 0; k < 9; ++k) {
        const u64 s0 = splat2(nA[k]);
        const u64 s1 = splat2(nB[k]);
#pragma unroll
        for (int c2 = 0; c2 < 5; ++c2) {
            const u64 wk = wp[c2 * 9 + k];
            a0[c2] = (k == 0) ? fma2(wk, s0, qr0p[c2]) : fma2(wk, s0, a0[c2]);
            a1[c2] = (k == 0) ? fma2(wk, s1, qr1p[c2]) : fma2(wk, s1, a1[c2]);
        }
    }

    const int s1i = (int)Sb[64];
    const int s2i = (int)Sb[65];
    const int psel = s1i * 8 + s2i;
    if (lane == (psel & 31)) {
        const bool hi = psel >= 32;
        float lg[8];
#pragma unroll
        for (int j = 0; j < 8; ++j) lg[j] = 0.f;
#pragma unroll
        for (int c2 = 0; c2 < 5; ++c2) {
            const float2 q = unpack2(hi ? a1[c2] : a0[c2]);
#pragma unroll
            for (int j = 0; j < 8; ++j) {
                lg[j] = fmaf(q.x, __ldg(&Wfc[j * 10 + 2 * c2]), lg[j]);
                lg[j] = fmaf(q.y, __ldg(&Wfc[j * 10 + 2 * c2 + 1]), lg[j]);
            }
        }
#pragma unroll
        for (int j = 0; j < 8; ++j) out[(long long)b * 8 + j] = lg[j];
    }
}

extern "C" void kernel_launch(void* const* d_in, const int* in_sizes, int n_in,
                              void* d_out, int out_size) {
    const float* S   = (const float*)d_in[0];
    const float* Wh  = (const float*)d_in[1];
    const float* bh  = (const float*)d_in[2];
    const float* Wr  = (const float*)d_in[3];
    const float* Wq  = (const float*)d_in[4];
    const float* w   = (const float*)d_in[5];
    const float* Wfc = (const float*)d_in[6];
    float* out = (float*)d_out;

    const int B = in_sizes[0] / 66;
    const int grid = (B + NWARP - 1) / NWARP;
    vin_kernel<<<grid, NWARP * 32>>>(S, Wh, bh, Wr, Wq, w, Wfc, out, B);
}

// round 7
// speedup vs baseline: 1.7107x; 1.2112x over previous
#include <cuda_runtime.h>

typedef unsigned long long u64;

#define LH 150
#define LQ 10
#define KI 10
#define NWARP 12

// ---- packed f32x2 helpers -------------------------------------------------
__device__ __forceinline__ u64 fma2(u64 a, u64 b, u64 c) {
    u64 d;
    asm("fma.rn.f32x2 %0, %1, %2, %3;" : "=l"(d) : "l"(a), "l"(b), "l"(c));
    return d;
}
__device__ __forceinline__ u64 pack2(float lo, float hi) {
    u64 r;
    asm("mov.b64 %0, {%1, %2};" : "=l"(r) : "f"(lo), "f"(hi));
    return r;
}
__device__ __forceinline__ u64 splat2(float x) {
    u64 r;
    asm("mov.b64 %0, {%1, %1};" : "=l"(r) : "f"(x));
    return r;
}
__device__ __forceinline__ float2 unpack2(u64 p) {
    float2 v;
    asm("mov.b64 {%0, %1}, %2;" : "=f"(v.x), "=f"(v.y) : "l"(p));
    return v;
}

// Vertical-pair register stencil. Lane l = (y = l>>3, x = l&7) owns
// vA = v(2y, x), vB = v(2y+1, x)  (two vertically adjacent rows).
// Window rows for A: {N, vA, vB}; for B: {vA, vB, S} -- the pair shares 6/9
// window values, so the halo needs only 10 unconditional shuffles:
//   N = vB of lane-8, S = vA of lane+8, plus W/E (shfl +-1) of {N, vA, vB, S}.
// Boundary zeros are applied AFTER each shuffle (plain selects, no divergent
// branches around shfl.sync).
// Output sv[12] = {WN,N,EN, WA,vA,EA, WB,vB,EB, WS,S,ES} as f32x2 splats:
// pixel A's tap k uses sv[k], pixel B's tap k uses sv[k+3].
__device__ __forceinline__ void stencil12(float vA, float vB, int lane,
                                          int y0, int x0, u64* sv) {
    const unsigned m = 0xffffffffu;
    float N  = __shfl_sync(m, vB, (lane + 24) & 31);
    float Sv = __shfl_sync(m, vA, (lane + 8) & 31);
    N  = y0 ? N : 0.f;            // row -1 = 0
    Sv = (y0 < 3) ? Sv : 0.f;     // row  8 = 0
    const int lw = (lane + 31) & 31, le = (lane + 1) & 31;
    float WN = __shfl_sync(m, N,  lw);
    float WA = __shfl_sync(m, vA, lw);
    float WB = __shfl_sync(m, vB, lw);
    float WS = __shfl_sync(m, Sv, lw);
    float EN = __shfl_sync(m, N,  le);
    float EA = __shfl_sync(m, vA, le);
    float EB = __shfl_sync(m, vB, le);
    float ES = __shfl_sync(m, Sv, le);
    const bool hw = (x0 != 0), he = (x0 != 7);
    WN = hw ? WN : 0.f; WA = hw ? WA : 0.f; WB = hw ? WB : 0.f; WS = hw ? WS : 0.f;
    EN = he ? EN : 0.f; EA = he ? EA : 0.f; EB = he ? EB : 0.f; ES = he ? ES : 0.f;
    sv[0] = splat2(WN); sv[1]  = splat2(N);  sv[2]  = splat2(EN);
    sv[3] = splat2(WA); sv[4]  = splat2(vA); sv[5]  = splat2(EA);
    sv[6] = splat2(WB); sv[7]  = splat2(vB); sv[8]  = splat2(EB);
    sv[9] = splat2(WS); sv[10] = splat2(Sv); sv[11] = splat2(ES);
}

// One warp per batch element; fully register-resident iteration loop
// (no smem access, no barriers). Channel-paired packed weights in 90 regs.
__global__ __launch_bounds__(NWARP * 32)
void vin_kernel(const float* __restrict__ S,
                const float* __restrict__ Wh,
                const float* __restrict__ bh,
                const float* __restrict__ Wr,
                const float* __restrict__ Wq,
                const float* __restrict__ w,
                const float* __restrict__ Wfc,
                float* __restrict__ out, int B) {
    __shared__ float sweff[10];
    __shared__ u64 wsh[45];    // packed transition weights {w[2c2][k], w[2c2+1][k]}
    __shared__ u64 wqsh[45];   // packed Wq, same layout

    const int tid = threadIdx.x;
    const int warp = tid >> 5;
    const int lane = tid & 31;

    // One-time staging of packed weights
    if (tid < 45) {
        const int c2 = tid / 9, k = tid % 9;
        wsh[tid] = pack2(__ldg(&w[(2 * c2) * 9 + k]),
                         __ldg(&w[(2 * c2 + 1) * 9 + k]));
    } else if (tid < 90) {
        const int t = tid - 45;
        const int c2 = t / 9, k = t % 9;
        wqsh[t] = pack2(__ldg(&Wq[(2 * c2) * 9 + k]),
                        __ldg(&Wq[(2 * c2 + 1) * 9 + k]));
    }
    // weff: collapse 150-ch hidden conv + 1x1 readout (warp j -> output j)
    if (warp < 10) {
        float acc = 0.f;
        for (int c = lane; c < LH; c += 32) {
            float x = (warp < 9) ? __ldg(&Wh[c * 9 + warp]) : __ldg(&bh[c]);
            acc = fmaf(__ldg(&Wr[c]), x, acc);
        }
#pragma unroll
        for (int off = 16; off >= 1; off >>= 1)
            acc += __shfl_xor_sync(0xffffffffu, acc, off);
        if (lane == 0) sweff[warp] = acc;
    }
    __syncthreads();

    const int b = blockIdx.x * NWARP + warp;
    if (b >= B) return;                    // warp-uniform; no syncs below
    const float* Sb = S + (long long)b * 66;

    const int y0 = lane >> 3, x0 = lane & 7;

    // Per-warp register copy of packed transition weights (broadcast LDS, once)
    u64 wp[45];
#pragma unroll
    for (int i = 0; i < 45; ++i) wp[i] = wsh[i];

    // X in registers: vA = row 2y, vB = row 2y+1 of column x
    float vA = Sb[16 * y0 + x0];
    float vB = Sb[16 * y0 + 8 + x0];

    u64 sv[12];

    // r = conv(X, W_eff, pad=1) + b_eff
    stencil12(vA, vB, lane, y0, x0, sv);
    float r0 = sweff[9], r1 = r0;
#pragma unroll
    for (int k = 0; k < 9; ++k) {
        r0 = fmaf(sweff[k], unpack2(sv[k]).x, r0);
        r1 = fmaf(sweff[k], unpack2(sv[k + 3]).x, r1);
    }

    // qr[c] = conv(r, Wq[c], pad=1)  (loop-invariant, channel-packed)
    u64 qr0p[5], qr1p[5];
    stencil12(r0, r1, lane, y0, x0, sv);
#pragma unroll
    for (int k = 0; k < 9; ++k) {
#pragma unroll
        for (int c2 = 0; c2 < 5; ++c2) {
            const u64 wq = wqsh[c2 * 9 + k];          // broadcast LDS, one-time
            qr0p[c2] = (k == 0) ? fma2(wq, sv[k], 0ull) : fma2(wq, sv[k], qr0p[c2]);
            qr1p[c2] = (k == 0) ? fma2(wq, sv[k + 3], 0ull) : fma2(wq, sv[k + 3], qr1p[c2]);
        }
    }

    // v = max_c qr
    {
        float2 t0 = unpack2(qr0p[0]), t1 = unpack2(qr1p[0]);
        vA = fmaxf(t0.x, t0.y); vB = fmaxf(t1.x, t1.y);
#pragma unroll
        for (int c2 = 1; c2 < 5; ++c2) {
            t0 = unpack2(qr0p[c2]); t1 = unpack2(qr1p[c2]);
            vA = fmaxf(vA, fmaxf(t0.x, t0.y));
            vB = fmaxf(vB, fmaxf(t1.x, t1.y));
        }
    }

    // K-1 = 9 sweeps: v <- max_c( qr[c] + conv(v, w[c]) ), all in registers
#pragma unroll 1
    for (int it = 0; it < KI - 1; ++it) {
        stencil12(vA, vB, lane, y0, x0, sv);
        u64 a0[5], a1[5];
#pragma unroll
        for (int k = 0; k < 9; ++k) {
#pragma unroll
            for (int c2 = 0; c2 < 5; ++c2) {
                const u64 wk = wp[c2 * 9 + k];
                a0[c2] = (k == 0) ? fma2(wk, sv[k], qr0p[c2])
                                  : fma2(wk, sv[k], a0[c2]);
                a1[c2] = (k == 0) ? fma2(wk, sv[k + 3], qr1p[c2])
                                  : fma2(wk, sv[k + 3], a1[c2]);
            }
        }
        float2 t0 = unpack2(a0[0]), t1 = unpack2(a1[0]);
        float m0 = fmaxf(t0.x, t0.y), m1 = fmaxf(t1.x, t1.y);
#pragma unroll
        for (int c2 = 1; c2 < 5; ++c2) {
            t0 = unpack2(a0[c2]); t1 = unpack2(a1[c2]);
            m0 = fmaxf(m0, fmaxf(t0.x, t0.y));
            m1 = fmaxf(m1, fmaxf(t1.x, t1.y));
        }
        vA = m0; vB = m1;
    }

    // Final q = qr + conv(v, w)  (no max), then pixel-select + FC head
    u64 a0[5], a1[5];
    stencil12(vA, vB, lane, y0, x0, sv);
#pragma unroll
    for (int k = 0; k < 9; ++k) {
#pragma unroll
        for (int c2 = 0; c2 < 5; ++c2) {
            const u64 wk = wp[c2 * 9 + k];
            a0[c2] = (k == 0) ? fma2(wk, sv[k], qr0p[c2]) : fma2(wk, sv[k], a0[c2]);
            a1[c2] = (k == 0) ? fma2(wk, sv[k + 3], qr1p[c2]) : fma2(wk, sv[k + 3], a1[c2]);
        }
    }

    // Selected pixel (s1=row, s2=col) lives in lane (s1>>1)*8 + s2,
    // half A if s1 even else half B.
    const int s1i = (int)Sb[64];
    const int s2i = (int)Sb[65];
    const int lsel = (s1i >> 1) * 8 + s2i;
    if (lane == lsel) {
        const bool hiB = (s1i & 1) != 0;
        float lg[8];
#pragma unroll
        for (int j = 0; j < 8; ++j) lg[j] = 0.f;
#pragma unroll
        for (int c2 = 0; c2 < 5; ++c2) {
            const float2 q = unpack2(hiB ? a1[c2] : a0[c2]);
#pragma unroll
            for (int j = 0; j < 8; ++j) {
                lg[j] = fmaf(q.x, __ldg(&Wfc[j * 10 + 2 * c2]), lg[j]);
                lg[j] = fmaf(q.y, __ldg(&Wfc[j * 10 + 2 * c2 + 1]), lg[j]);
            }
        }
#pragma unroll
        for (int j = 0; j < 8; ++j) out[(long long)b * 8 + j] = lg[j];
    }
}

extern "C" void kernel_launch(void* const* d_in, const int* in_sizes, int n_in,
                              void* d_out, int out_size) {
    const float* S   = (const float*)d_in[0];
    const float* Wh  = (const float*)d_in[1];
    const float* bh  = (const float*)d_in[2];
    const float* Wr  = (const float*)d_in[3];
    const float* Wq  = (const float*)d_in[4];
    const float* w   = (const float*)d_in[5];
    const float* Wfc = (const float*)d_in[6];
    float* out = (float*)d_out;

    const int B = in_sizes[0] / 66;
    const int grid = (B + NWARP - 1) / NWARP;
    vin_kernel<<<grid, NWARP * 32>>>(S, Wh, bh, Wr, Wq, w, Wfc, out, B);
}